// round 14
// baseline (speedup 1.0000x reference)
#include <cuda_runtime.h>

// DynamicHead: per-sample grouped 1x1 conv (KERNEL_SIZE=1, PAD=0).
// f:      [B=8, C=400, H=128, W=128] fp32   (210 MB, read exactly once)
// kernel: [B=8, N=50, CPG=8]         fp32   (12.8 KB)
// out:    [B=8, N=50, H=128, W=128]  fp32   (26 MB, written once)
//
// FINAL (converged, = R9 config). HBM-bound. Full map of the DRAM
// page-locality vs achieved-MLP tradeoff (kernel-side noise ~±200 GB/s):
//   1216 CTAs: 6318 | 800: 6382/6192 (plateau) | 640: 5872 | 400: 5479
// Plateau spans ~800-1216 CTAs; cliff below 800 (LSU/MLP starvation).
// This config sits mid-plateau with perfect load balance:
//   100 groups x 8 sub-CTAs = 800 CTAs; each group handles exactly 4
//   (b,n) tiles; each sub-CTA consumes an 8KB contiguous window of each
//   of the 8 input planes per visit (2-iteration dwell).
// Per-thread: 8 independent LDG.128 (MLP=8), default cache policy,
// warp-uniform L1-broadcast weights.
// Ruled out: .cs hints (-2.4%), 256-bit LDG (-5%), occupancy/wave shaping
// (neutral), tensor cores / TMA (AI=0.44 FLOP/B; LTS path-independent).

#define N_      50
#define HW4_    4096                      // 128*128/4 float4 per plane
#define BN_     400
#define TPB_    256
#define GRPW_   8                         // sub-CTAs per group
#define NGRP_   100                       // 100 groups -> exactly 4 bn each

__global__ __launch_bounds__(TPB_)
void dynhead_1x1_bal(const float4* __restrict__ f4,
                     const float* __restrict__ kern,
                     float4* __restrict__ o4) {
    const int g   = blockIdx.x >> 3;         // group id (0..99)
    const int sub = blockIdx.x & (GRPW_-1);  // 0..7 within group

#pragma unroll
    for (int v = 0; v < 4; v++) {            // exactly 4 bn per group
        const int bn = g + v * NGRP_;
        const int b = bn / N_;
        const int n = bn - b * N_;

        // 8 group weights: warp-uniform, L1 broadcast.
        const float* kp = kern + bn * 8;
        const float w0 = __ldg(kp + 0), w1 = __ldg(kp + 1);
        const float w2 = __ldg(kp + 2), w3 = __ldg(kp + 3);
        const float w4 = __ldg(kp + 4), w5 = __ldg(kp + 5);
        const float w6 = __ldg(kp + 6), w7 = __ldg(kp + 7);

        const float4* __restrict__ fp = f4 + ((b * 400 + n * 8) << 12);
        float4* __restrict__ op = o4 + (bn << 12);

        // sub-CTA owns contiguous pos range [sub*512, (sub+1)*512): 8KB/plane.
        int pos = sub * 512 + threadIdx.x;
#pragma unroll
        for (int i = 0; i < 2; i++, pos += TPB_) {
            const float4 v0 = fp[0 * HW4_ + pos];
            const float4 v1 = fp[1 * HW4_ + pos];
            const float4 v2 = fp[2 * HW4_ + pos];
            const float4 v3 = fp[3 * HW4_ + pos];
            const float4 v4 = fp[4 * HW4_ + pos];
            const float4 v5 = fp[5 * HW4_ + pos];
            const float4 v6 = fp[6 * HW4_ + pos];
            const float4 v7 = fp[7 * HW4_ + pos];

            float4 acc;
            acc.x = v0.x * w0; acc.y = v0.y * w0; acc.z = v0.z * w0; acc.w = v0.w * w0;
            acc.x = fmaf(w1, v1.x, acc.x); acc.y = fmaf(w1, v1.y, acc.y);
            acc.z = fmaf(w1, v1.z, acc.z); acc.w = fmaf(w1, v1.w, acc.w);
            acc.x = fmaf(w2, v2.x, acc.x); acc.y = fmaf(w2, v2.y, acc.y);
            acc.z = fmaf(w2, v2.z, acc.z); acc.w = fmaf(w2, v2.w, acc.w);
            acc.x = fmaf(w3, v3.x, acc.x); acc.y = fmaf(w3, v3.y, acc.y);
            acc.z = fmaf(w3, v3.z, acc.z); acc.w = fmaf(w3, v3.w, acc.w);
            acc.x = fmaf(w4, v4.x, acc.x); acc.y = fmaf(w4, v4.y, acc.y);
            acc.z = fmaf(w4, v4.z, acc.z); acc.w = fmaf(w4, v4.w, acc.w);
            acc.x = fmaf(w5, v5.x, acc.x); acc.y = fmaf(w5, v5.y, acc.y);
            acc.z = fmaf(w5, v5.z, acc.z); acc.w = fmaf(w5, v5.w, acc.w);
            acc.x = fmaf(w6, v6.x, acc.x); acc.y = fmaf(w6, v6.y, acc.y);
            acc.z = fmaf(w6, v6.z, acc.z); acc.w = fmaf(w6, v6.w, acc.w);
            acc.x = fmaf(w7, v7.x, acc.x); acc.y = fmaf(w7, v7.y, acc.y);
            acc.z = fmaf(w7, v7.z, acc.z); acc.w = fmaf(w7, v7.w, acc.w);

            op[pos] = acc;
        }
    }
}

extern "C" void kernel_launch(void* const* d_in, const int* in_sizes, int n_in,
                              void* d_out, int out_size) {
    const float4* f4  = (const float4*)d_in[0];
    const float* kern = (const float*)d_in[1];
    float4* o4        = (float4*)d_out;

    dim3 grid(NGRP_ * GRPW_);   // 800 CTAs, perfectly balanced (4 bn each)
    dynhead_1x1_bal<<<grid, TPB_>>>(f4, kern, o4);
}

// round 15
// speedup vs baseline: 1.0008x; 1.0008x over previous
#include <cuda_runtime.h>

// DynamicHead: per-sample grouped 1x1 conv (KERNEL_SIZE=1, PAD=0).
// f:      [B=8, C=400, H=128, W=128] fp32   (210 MB, read exactly once)
// kernel: [B=8, N=50, CPG=8]         fp32   (12.8 KB)
// out:    [B=8, N=50, H=128, W=128]  fp32   (26 MB, written once)
//
// FINAL (converged; held across R12-R14 rebenches: kernel 35.5-36.5us,
// HBM 6.2-6.4 TB/s, noise +-1us). HBM-bound. DRAM page-locality vs
// achieved-MLP curve fully mapped:
//   1216 CTAs: 6318 | 800: 6382/6280/6192 (plateau peak) | 640: 5872 | 400: 5479
// Config: 100 groups x 8 sub-CTAs = 800 CTAs; each group handles exactly
// 4 (b,n) tiles (perfect balance); each sub-CTA consumes an 8KB contiguous
// window of each of the 8 input planes per visit (2-iteration dwell).
// Per-thread: 8 independent LDG.128 (MLP=8), default cache policy,
// warp-uniform L1-broadcast weights.
// Ruled out with signal: stream count <800 (-8..14%), 256-bit LDG (-5%),
// .cs hints (-2.4%). Neutral: occupancy 63-96%, wave shaping, CTA mapping.
// Irrelevant: tensor cores / TMA (AI=0.44 FLOP/B; LTS path-independent).

#define N_      50
#define HW4_    4096                      // 128*128/4 float4 per plane
#define BN_     400
#define TPB_    256
#define GRPW_   8                         // sub-CTAs per group
#define NGRP_   100                       // 100 groups -> exactly 4 bn each

__global__ __launch_bounds__(TPB_)
void dynhead_1x1_bal(const float4* __restrict__ f4,
                     const float* __restrict__ kern,
                     float4* __restrict__ o4) {
    const int g   = blockIdx.x >> 3;         // group id (0..99)
    const int sub = blockIdx.x & (GRPW_-1);  // 0..7 within group

#pragma unroll
    for (int v = 0; v < 4; v++) {            // exactly 4 bn per group
        const int bn = g + v * NGRP_;
        const int b = bn / N_;
        const int n = bn - b * N_;

        // 8 group weights: warp-uniform, L1 broadcast.
        const float* kp = kern + bn * 8;
        const float w0 = __ldg(kp + 0), w1 = __ldg(kp + 1);
        const float w2 = __ldg(kp + 2), w3 = __ldg(kp + 3);
        const float w4 = __ldg(kp + 4), w5 = __ldg(kp + 5);
        const float w6 = __ldg(kp + 6), w7 = __ldg(kp + 7);

        const float4* __restrict__ fp = f4 + ((b * 400 + n * 8) << 12);
        float4* __restrict__ op = o4 + (bn << 12);

        // sub-CTA owns contiguous pos range [sub*512, (sub+1)*512): 8KB/plane.
        int pos = sub * 512 + threadIdx.x;
#pragma unroll
        for (int i = 0; i < 2; i++, pos += TPB_) {
            const float4 v0 = fp[0 * HW4_ + pos];
            const float4 v1 = fp[1 * HW4_ + pos];
            const float4 v2 = fp[2 * HW4_ + pos];
            const float4 v3 = fp[3 * HW4_ + pos];
            const float4 v4 = fp[4 * HW4_ + pos];
            const float4 v5 = fp[5 * HW4_ + pos];
            const float4 v6 = fp[6 * HW4_ + pos];
            const float4 v7 = fp[7 * HW4_ + pos];

            float4 acc;
            acc.x = v0.x * w0; acc.y = v0.y * w0; acc.z = v0.z * w0; acc.w = v0.w * w0;
            acc.x = fmaf(w1, v1.x, acc.x); acc.y = fmaf(w1, v1.y, acc.y);
            acc.z = fmaf(w1, v1.z, acc.z); acc.w = fmaf(w1, v1.w, acc.w);
            acc.x = fmaf(w2, v2.x, acc.x); acc.y = fmaf(w2, v2.y, acc.y);
            acc.z = fmaf(w2, v2.z, acc.z); acc.w = fmaf(w2, v2.w, acc.w);
            acc.x = fmaf(w3, v3.x, acc.x); acc.y = fmaf(w3, v3.y, acc.y);
            acc.z = fmaf(w3, v3.z, acc.z); acc.w = fmaf(w3, v3.w, acc.w);
            acc.x = fmaf(w4, v4.x, acc.x); acc.y = fmaf(w4, v4.y, acc.y);
            acc.z = fmaf(w4, v4.z, acc.z); acc.w = fmaf(w4, v4.w, acc.w);
            acc.x = fmaf(w5, v5.x, acc.x); acc.y = fmaf(w5, v5.y, acc.y);
            acc.z = fmaf(w5, v5.z, acc.z); acc.w = fmaf(w5, v5.w, acc.w);
            acc.x = fmaf(w6, v6.x, acc.x); acc.y = fmaf(w6, v6.y, acc.y);
            acc.z = fmaf(w6, v6.z, acc.z); acc.w = fmaf(w6, v6.w, acc.w);
            acc.x = fmaf(w7, v7.x, acc.x); acc.y = fmaf(w7, v7.y, acc.y);
            acc.z = fmaf(w7, v7.z, acc.z); acc.w = fmaf(w7, v7.w, acc.w);

            op[pos] = acc;
        }
    }
}

extern "C" void kernel_launch(void* const* d_in, const int* in_sizes, int n_in,
                              void* d_out, int out_size) {
    const float4* f4  = (const float4*)d_in[0];
    const float* kern = (const float*)d_in[1];
    float4* o4        = (float4*)d_out;

    dim3 grid(NGRP_ * GRPW_);   // 800 CTAs, perfectly balanced (4 bn each)
    dynhead_1x1_bal<<<grid, TPB_>>>(f4, kern, o4);
}

// round 16
// speedup vs baseline: 1.0016x; 1.0008x over previous
#include <cuda_runtime.h>

// DynamicHead: per-sample grouped 1x1 conv (KERNEL_SIZE=1, PAD=0).
// f:      [B=8, C=400, H=128, W=128] fp32   (210 MB, read exactly once)
// kernel: [B=8, N=50, CPG=8]         fp32   (12.8 KB)
// out:    [B=8, N=50, H=128, W=128]  fp32   (26 MB, written once)
//
// R15: burst-length extension at the proven-optimal concurrency.
// Stream count is fixed by CTA count (each CTA = 8 plane-streams); the
// group geometry sets contiguous run length per stream. Evidence:
// 4KB runs (R8) < 8KB runs (R7/R9). This round: 200 groups x 4 sub-CTAs
// = 800 CTAs (unchanged, peak), but each sub-CTA owns a 16KB contiguous
// window per plane (4-iteration dwell). Perfect balance: 2 bn per group.
// Per-thread structure unchanged: 8 independent LDG.128 (MLP=8),
// default cache policy, warp-uniform L1-broadcast weights.

#define N_      50
#define HW4_    4096                      // 128*128/4 float4 per plane
#define BN_     400
#define TPB_    256
#define GRPW_   4                         // sub-CTAs per group
#define NGRP_   200                       // 200 groups -> exactly 2 bn each

__global__ __launch_bounds__(TPB_)
void dynhead_1x1_b16k(const float4* __restrict__ f4,
                      const float* __restrict__ kern,
                      float4* __restrict__ o4) {
    const int g   = blockIdx.x >> 2;         // group id (0..199)
    const int sub = blockIdx.x & (GRPW_-1);  // 0..3 within group

#pragma unroll
    for (int v = 0; v < 2; v++) {            // exactly 2 bn per group
        const int bn = g + v * NGRP_;
        const int b = bn / N_;
        const int n = bn - b * N_;

        // 8 group weights: warp-uniform, L1 broadcast.
        const float* kp = kern + bn * 8;
        const float w0 = __ldg(kp + 0), w1 = __ldg(kp + 1);
        const float w2 = __ldg(kp + 2), w3 = __ldg(kp + 3);
        const float w4 = __ldg(kp + 4), w5 = __ldg(kp + 5);
        const float w6 = __ldg(kp + 6), w7 = __ldg(kp + 7);

        const float4* __restrict__ fp = f4 + ((b * 400 + n * 8) << 12);
        float4* __restrict__ op = o4 + (bn << 12);

        // sub-CTA owns contiguous pos range [sub*1024, (sub+1)*1024):
        // 16KB contiguous per plane, consumed over a 4-iteration dwell.
        int pos = sub * 1024 + threadIdx.x;
#pragma unroll
        for (int i = 0; i < 4; i++, pos += TPB_) {
            const float4 v0 = fp[0 * HW4_ + pos];
            const float4 v1 = fp[1 * HW4_ + pos];
            const float4 v2 = fp[2 * HW4_ + pos];
            const float4 v3 = fp[3 * HW4_ + pos];
            const float4 v4 = fp[4 * HW4_ + pos];
            const float4 v5 = fp[5 * HW4_ + pos];
            const float4 v6 = fp[6 * HW4_ + pos];
            const float4 v7 = fp[7 * HW4_ + pos];

            float4 acc;
            acc.x = v0.x * w0; acc.y = v0.y * w0; acc.z = v0.z * w0; acc.w = v0.w * w0;
            acc.x = fmaf(w1, v1.x, acc.x); acc.y = fmaf(w1, v1.y, acc.y);
            acc.z = fmaf(w1, v1.z, acc.z); acc.w = fmaf(w1, v1.w, acc.w);
            acc.x = fmaf(w2, v2.x, acc.x); acc.y = fmaf(w2, v2.y, acc.y);
            acc.z = fmaf(w2, v2.z, acc.z); acc.w = fmaf(w2, v2.w, acc.w);
            acc.x = fmaf(w3, v3.x, acc.x); acc.y = fmaf(w3, v3.y, acc.y);
            acc.z = fmaf(w3, v3.z, acc.z); acc.w = fmaf(w3, v3.w, acc.w);
            acc.x = fmaf(w4, v4.x, acc.x); acc.y = fmaf(w4, v4.y, acc.y);
            acc.z = fmaf(w4, v4.z, acc.z); acc.w = fmaf(w4, v4.w, acc.w);
            acc.x = fmaf(w5, v5.x, acc.x); acc.y = fmaf(w5, v5.y, acc.y);
            acc.z = fmaf(w5, v5.z, acc.z); acc.w = fmaf(w5, v5.w, acc.w);
            acc.x = fmaf(w6, v6.x, acc.x); acc.y = fmaf(w6, v6.y, acc.y);
            acc.z = fmaf(w6, v6.z, acc.z); acc.w = fmaf(w6, v6.w, acc.w);
            acc.x = fmaf(w7, v7.x, acc.x); acc.y = fmaf(w7, v7.y, acc.y);
            acc.z = fmaf(w7, v7.z, acc.z); acc.w = fmaf(w7, v7.w, acc.w);

            op[pos] = acc;
        }
    }
}

extern "C" void kernel_launch(void* const* d_in, const int* in_sizes, int n_in,
                              void* d_out, int out_size) {
    const float4* f4  = (const float4*)d_in[0];
    const float* kern = (const float*)d_in[1];
    float4* o4        = (float4*)d_out;

    dim3 grid(NGRP_ * GRPW_);   // 800 CTAs, perfectly balanced (2 bn each)
    dynhead_1x1_b16k<<<grid, TPB_>>>(f4, kern, o4);
}